// round 8
// baseline (speedup 1.0000x reference)
#include <cuda_runtime.h>
#include <math.h>
#include <stdint.h>

// Problem constants
#define BATCH   8
#define SEQ     2048
#define HID     1024
#define NPB     (SEQ * HID)        // 2,097,152 elements per batch
#define VEC_PB  (NPB / 4)          // 524,288 float4 per batch
#define TOTALV  (BATCH * VEC_PB)   // 4,194,304 float4 total
#define RANK0   1048576u           // 0-indexed ascending rank of threshold (N - k)
#define NBINS   65536              // single-pass digit = bits[31:16]
#define NWORDS  (NBINS / 2)        // packed 16-bit counters (128 KB smem)
#define HGRID   64                 // hist blocks per batch (32 rows each)
#define FBLK    128                // final blocks per batch (16 rows each)

// Static scratch (no runtime allocation allowed)
__device__ __align__(16) float    g_imp5[5 * HID];        // sigmoid(band)*sigmoid(dim)
__device__ unsigned               g_hist[BATCH][NBINS];   // 2 MB
__device__ float                  g_thr[BATCH];

__device__ __forceinline__ float sigmoidf_fast(float x) {
    return 1.0f / (1.0f + __expf(-x));
}

// band(t): 0 for t<128, else floor(log2(t>>7)) + 1   (T=2048, L=4)
__device__ __forceinline__ int band_of(int t) {
    return (t >= 128) ? (32 - __clz(t >> 7)) : 0;
}

// ---------------------------------------------------------------------------
// setup: zero 2MB global histogram, build importance table
// ---------------------------------------------------------------------------
__global__ void __launch_bounds__(1024) setup_kernel(const float* __restrict__ bi,
                                                     const float* __restrict__ di) {
    int i = blockIdx.x * blockDim.x + threadIdx.x;   // 512 * 1024 = 524288 threads
    ((uint4*)g_hist)[i] = make_uint4(0, 0, 0, 0);    // 524288 * 16B = 8MB? no: 2MB/16 = 131072
    // NOTE: grid sized so only first 131072 threads write uint4 (guard below)
}

// (replaced by guarded version below — see setup2_kernel)
__global__ void __launch_bounds__(256) setup2_kernel(const float* __restrict__ bi,
                                                     const float* __restrict__ di) {
    int i = blockIdx.x * blockDim.x + threadIdx.x;
    if (i < BATCH * NBINS / 4)
        ((uint4*)g_hist)[i] = make_uint4(0, 0, 0, 0);
    if (i < 5 * HID) {
        float sb = sigmoidf_fast(bi[i]);
        float sd = sigmoidf_fast(di[i & (HID - 1)]);
        g_imp5[i] = sb * sd;
    }
}

// ---------------------------------------------------------------------------
// single histogram pass: 64K bins = bits[31:16], packed 16-bit smem counters.
// grid (HGRID, BATCH) x 1024; block = 32 contiguous rows (single band);
// thread = one float4 column -> imp4 is a per-thread constant.
// ---------------------------------------------------------------------------
#define HACC(val)                                                           \
    {                                                                       \
        unsigned bin = __float_as_uint(val) >> 16;                          \
        atomicAdd(&sh[bin >> 1], (bin & 1u) ? 65536u : 1u);                 \
    }

#define HPROC4(c)                                                           \
    HACC(imp.x * fabsf((c).x));                                             \
    HACC(imp.y * fabsf((c).y));                                             \
    HACC(imp.z * fabsf((c).z));                                             \
    HACC(imp.w * fabsf((c).w));

__global__ void __launch_bounds__(1024) hist_kernel(const float4* __restrict__ coeffs) {
    extern __shared__ unsigned sh[];                 // NWORDS = 32768 words (128 KB)
    const int tid = threadIdx.x;

    for (int i = tid; i < NWORDS; i += 1024) sh[i] = 0;
    __syncthreads();

    const int batch = blockIdx.y;
    const int band = band_of(blockIdx.x << 5);       // 32 rows/block; boundaries are multiples of 32
    const float4 imp = *reinterpret_cast<const float4*>(&g_imp5[band * HID + ((tid & 255) << 2)]);
    const float4* p = coeffs + (size_t)batch * VEC_PB + (size_t)blockIdx.x * 8192 + tid;

    #pragma unroll
    for (int it = 0; it < 8; it += 4) {
        float4 c0 = __ldg(p + (it + 0) * 1024);
        float4 c1 = __ldg(p + (it + 1) * 1024);
        float4 c2 = __ldg(p + (it + 2) * 1024);
        float4 c3 = __ldg(p + (it + 3) * 1024);
        HPROC4(c0);
        HPROC4(c1);
        HPROC4(c2);
        HPROC4(c3);
    }
    __syncthreads();

    unsigned* gh = g_hist[batch];
    for (int i = tid; i < NWORDS; i += 1024) {
        unsigned w = sh[i];
        unsigned lo = w & 0xFFFFu;
        unsigned hi = w >> 16;
        if (lo) atomicAdd(&gh[2 * i], lo);
        if (hi) atomicAdd(&gh[2 * i + 1], hi);
    }
}

// ---------------------------------------------------------------------------
// select: one block of 1024 threads per batch over 64K bins.
// Threshold = midpoint of the selected 2^16-wide bin (rel err <= 2^-8).
// ---------------------------------------------------------------------------
__global__ void __launch_bounds__(1024) select_kernel() {
    __shared__ unsigned tw[32];
    const int b = blockIdx.x;
    const int tid = threadIdx.x;
    const int lane = tid & 31;
    const int wid = tid >> 5;
    const unsigned* __restrict__ h = g_hist[b];

    unsigned s = 0;
    #pragma unroll
    for (int j = 0; j < 64; j++) s += h[tid * 64 + j];

    // warp inclusive scan
    unsigned v = s;
    #pragma unroll
    for (int o = 1; o < 32; o <<= 1) {
        unsigned t = __shfl_up_sync(0xFFFFFFFFu, v, o);
        if (lane >= o) v += t;
    }
    if (lane == 31) tw[wid] = v;
    __syncthreads();

    if (wid == 0) {
        unsigned t = tw[lane];
        #pragma unroll
        for (int o = 1; o < 32; o <<= 1) {
            unsigned u = __shfl_up_sync(0xFFFFFFFFu, t, o);
            if (lane >= o) t += u;
        }
        tw[lane] = t;   // inclusive warp totals
    }
    __syncthreads();

    unsigned warp_excl = wid ? tw[wid - 1] : 0u;
    unsigned excl = warp_excl + (v - s);

    if (RANK0 >= excl && RANK0 < excl + s) {
        unsigned cum = excl;
        #pragma unroll 1
        for (int j = 0; j < 64; j++) {
            unsigned c = h[tid * 64 + j];
            if (RANK0 < cum + c) {
                unsigned bin = (unsigned)(tid * 64 + j);
                g_thr[b] = __uint_as_float((bin << 16) | 0x8000u);
                break;
            }
            cum += c;
        }
    }
}

// ---------------------------------------------------------------------------
// final: out[0..V)=coeffs*mask, out[V..2V)=mask, out[2V..3V)=importance.
// Block = 16 rows (single band): imp4 per-thread constant, written from regs.
// Streaming stores for the 192MB write side.
// ---------------------------------------------------------------------------
__global__ void __launch_bounds__(256) final_kernel(const float4* __restrict__ coeffs,
                                                    const float* __restrict__ temp,
                                                    float4* __restrict__ out) {
    const int tid = threadIdx.x;
    const int batch = blockIdx.y;
    const int band = band_of(blockIdx.x << 4);
    const float4 imp = *reinterpret_cast<const float4*>(&g_imp5[band * HID + (tid << 2)]);
    const float thr = g_thr[batch];
    const float inv_t = __frcp_rn(fabsf(__ldg(&temp[0])));

    const size_t vbase = (size_t)batch * VEC_PB + (size_t)blockIdx.x * (16 * 256) + tid;
    const float4* p = coeffs + vbase;

    #pragma unroll
    for (int r = 0; r < 16; r += 2) {
        float4 c0 = __ldg(p + (r + 0) * 256);
        float4 c1 = __ldg(p + (r + 1) * 256);

        float4 mk0, fl0, mk1, fl1;
        { float ci = imp.x * fabsf(c0.x); mk0.x = sigmoidf_fast((ci - thr) * inv_t); fl0.x = c0.x * mk0.x; }
        { float ci = imp.y * fabsf(c0.y); mk0.y = sigmoidf_fast((ci - thr) * inv_t); fl0.y = c0.y * mk0.y; }
        { float ci = imp.z * fabsf(c0.z); mk0.z = sigmoidf_fast((ci - thr) * inv_t); fl0.z = c0.z * mk0.z; }
        { float ci = imp.w * fabsf(c0.w); mk0.w = sigmoidf_fast((ci - thr) * inv_t); fl0.w = c0.w * mk0.w; }
        { float ci = imp.x * fabsf(c1.x); mk1.x = sigmoidf_fast((ci - thr) * inv_t); fl1.x = c1.x * mk1.x; }
        { float ci = imp.y * fabsf(c1.y); mk1.y = sigmoidf_fast((ci - thr) * inv_t); fl1.y = c1.y * mk1.y; }
        { float ci = imp.z * fabsf(c1.z); mk1.z = sigmoidf_fast((ci - thr) * inv_t); fl1.z = c1.z * mk1.z; }
        { float ci = imp.w * fabsf(c1.w); mk1.w = sigmoidf_fast((ci - thr) * inv_t); fl1.w = c1.w * mk1.w; }

        size_t ve0 = vbase + (size_t)(r + 0) * 256;
        size_t ve1 = vbase + (size_t)(r + 1) * 256;
        __stcs(&out[ve0], fl0);
        __stcs(&out[ve1], fl1);
        __stcs(&out[TOTALV + ve0], mk0);
        __stcs(&out[TOTALV + ve1], mk1);
        __stcs(&out[2 * TOTALV + ve0], imp);
        __stcs(&out[2 * TOTALV + ve1], imp);
    }
}

// ---------------------------------------------------------------------------
// launch
// ---------------------------------------------------------------------------
extern "C" void kernel_launch(void* const* d_in, const int* in_sizes, int n_in,
                              void* d_out, int out_size) {
    const float* coeffs = (const float*)d_in[0];
    const float* bi     = (const float*)d_in[1];
    const float* di     = (const float*)d_in[2];
    const float* temp   = (const float*)d_in[3];
    float* out = (float*)d_out;

    // opt-in to 128KB dynamic smem for the histogram kernel (host-side config,
    // not a stream op; safe under graph capture, idempotent)
    static bool configured = false;
    if (!configured) {
        cudaFuncSetAttribute(hist_kernel, cudaFuncAttributeMaxDynamicSharedMemorySize,
                             NWORDS * (int)sizeof(unsigned));
        configured = true;
    }

    // zero 2MB hist + build imp table: 131072 uint4 words + 5120 floats
    setup2_kernel<<<(BATCH * NBINS / 4 + 255) / 256, 256>>>(bi, di);

    dim3 hg(HGRID, BATCH);
    hist_kernel<<<hg, 1024, NWORDS * sizeof(unsigned)>>>((const float4*)coeffs);
    select_kernel<<<BATCH, 1024>>>();

    dim3 fg(FBLK, BATCH);
    final_kernel<<<fg, 256>>>((const float4*)coeffs, temp, (float4*)out);
}